// round 1
// baseline (speedup 1.0000x reference)
#include <cuda_runtime.h>
#include <math.h>

#define INF_F 1000000000000.0f

typedef unsigned long long u64;

// ---------------- scratch (no cudaMalloc allowed) ----------------
__device__ float g_qw[16 * 512 * 64];    // rope'd q
__device__ float g_kw[16 * 512 * 64];    // rope'd k
__device__ float g_bq[16 * 12 * 512];    // bias[:,0::2]/2  (indexed by n)
__device__ float g_bk[16 * 12 * 512];    // bias[:,1::2]/2  (indexed by m)
__device__ float g_sin[512 * 32];
__device__ float g_cos[512 * 32];

// ---------------- f32x2 packed-FMA helpers (Blackwell FFMA2) ------
__device__ __forceinline__ u64 pk2(float lo, float hi) {
    u64 r; asm("mov.b64 %0,{%1,%2};" : "=l"(r) : "f"(lo), "f"(hi)); return r;
}
__device__ __forceinline__ void fma2(u64 &c, u64 a, u64 b) {
    asm("fma.rn.f32x2 %0,%1,%2,%0;" : "+l"(c) : "l"(a), "l"(b));
}
__device__ __forceinline__ float2 up2(u64 v) {
    float2 f; asm("mov.b64 {%0,%1},%2;" : "=f"(f.x), "=f"(f.y) : "l"(v)); return f;
}

// ================= K0: rope tables =================
__global__ void k0_rope() {
    int idx = blockIdx.x * 256 + threadIdx.x;
    if (idx < 512 * 32) {
        int pos = idx >> 5, i = idx & 31;
        float e = (float)(2 * i) * (1.0f / 64.0f);
        float invf = 1.0f / powf(10000.0f, e);
        float fr = (float)pos * invf;
        g_sin[idx] = sinf(fr);
        g_cos[idx] = cosf(fr);
    }
}

// ================= K1: x = inputs@W1+b1, rope split, bias =================
// Grid: 128 blocks (64 rows each of the 8192-row GEMM). 128 threads.
// Tile: BM=64, BN=128 (full), BK=16. Microtile 8m x 8n via FFMA2 (m-pairs).
__global__ void __launch_bounds__(128) k1_gemm(
    const float* __restrict__ inp, const float* __restrict__ W1,
    const float* __restrict__ b1v, const float* __restrict__ W2,
    const float* __restrict__ b2v)
{
    __shared__ __align__(16) float sm[11520];   // 46080 B, reused across phases
    float* aT = sm;              // [16][68]  (A transposed, padded)
    float* bS = sm + 16 * 68;    // [16][128]

    int t = threadIdx.x;
    int tx = t & 15, ty = t >> 4;        // 16 x 8 thread grid
    int row0 = blockIdx.x * 64;
    int bidx = row0 >> 9;
    int pos0 = row0 & 511;
    int m0 = ty * 8, n0 = tx * 4;

    u64 acc[4][8];
#pragma unroll
    for (int p = 0; p < 4; p++)
#pragma unroll
        for (int j = 0; j < 8; j++) acc[p][j] = 0ULL;

    float4 apre[2], bpre[4];

    // ---- load chunk 0 ----
#pragma unroll
    for (int i = 0; i < 2; i++) {
        int idx = t + i * 128; int m = idx >> 2; int kq = (idx & 3) << 2;
        apre[i] = *(const float4*)(inp + (size_t)(row0 + m) * 1024 + kq);
    }
#pragma unroll
    for (int i = 0; i < 4; i++) {
        int idx = t + i * 128; int k = idx >> 5; int n4 = (idx & 31) << 2;
        bpre[i] = *(const float4*)(W1 + (size_t)k * 128 + n4);
    }
#pragma unroll
    for (int i = 0; i < 2; i++) {
        int idx = t + i * 128; int m = idx >> 2; int kq = (idx & 3) << 2;
        aT[(kq + 0) * 68 + m] = apre[i].x;
        aT[(kq + 1) * 68 + m] = apre[i].y;
        aT[(kq + 2) * 68 + m] = apre[i].z;
        aT[(kq + 3) * 68 + m] = apre[i].w;
    }
#pragma unroll
    for (int i = 0; i < 4; i++) {
        int idx = t + i * 128; int k = idx >> 5; int n4 = (idx & 31) << 2;
        *(float4*)(bS + k * 128 + n4) = bpre[i];
    }
    __syncthreads();

    for (int kc = 0; kc < 64; ++kc) {
        if (kc < 63) {
            int kb = (kc + 1) * 16;
#pragma unroll
            for (int i = 0; i < 2; i++) {
                int idx = t + i * 128; int m = idx >> 2; int kq = (idx & 3) << 2;
                apre[i] = *(const float4*)(inp + (size_t)(row0 + m) * 1024 + kb + kq);
            }
#pragma unroll
            for (int i = 0; i < 4; i++) {
                int idx = t + i * 128; int k = idx >> 5; int n4 = (idx & 31) << 2;
                bpre[i] = *(const float4*)(W1 + (size_t)(kb + k) * 128 + n4);
            }
        }
#pragma unroll
        for (int k = 0; k < 16; k++) {
            float4 alo = *(const float4*)(aT + k * 68 + m0);
            float4 ahi = *(const float4*)(aT + k * 68 + m0 + 4);
            float4 bl  = *(const float4*)(bS + k * 128 + n0);
            float4 bh  = *(const float4*)(bS + k * 128 + 64 + n0);
            u64 ap[4];
            ap[0] = pk2(alo.x, alo.y); ap[1] = pk2(alo.z, alo.w);
            ap[2] = pk2(ahi.x, ahi.y); ap[3] = pk2(ahi.z, ahi.w);
            float bb[8] = {bl.x, bl.y, bl.z, bl.w, bh.x, bh.y, bh.z, bh.w};
#pragma unroll
            for (int j = 0; j < 8; j++) {
                u64 bd = pk2(bb[j], bb[j]);
#pragma unroll
                for (int p = 0; p < 4; p++) fma2(acc[p][j], ap[p], bd);
            }
        }
        __syncthreads();
        if (kc < 63) {
#pragma unroll
            for (int i = 0; i < 2; i++) {
                int idx = t + i * 128; int m = idx >> 2; int kq = (idx & 3) << 2;
                aT[(kq + 0) * 68 + m] = apre[i].x;
                aT[(kq + 1) * 68 + m] = apre[i].y;
                aT[(kq + 2) * 68 + m] = apre[i].z;
                aT[(kq + 3) * 68 + m] = apre[i].w;
            }
#pragma unroll
            for (int i = 0; i < 4; i++) {
                int idx = t + i * 128; int k = idx >> 5; int n4 = (idx & 31) << 2;
                *(float4*)(bS + k * 128 + n4) = bpre[i];
            }
            __syncthreads();
        }
    }

    // ---- epilogue: unpack + b1 ----
    float x[8][8];
#pragma unroll
    for (int p = 0; p < 4; p++)
#pragma unroll
        for (int j = 0; j < 8; j++) {
            float2 v = up2(acc[p][j]);
            x[2 * p][j] = v.x;
            x[2 * p + 1][j] = v.y;
        }
    float bc[8];
#pragma unroll
    for (int j = 0; j < 4; j++) {
        bc[j]     = __ldg(b1v + n0 + j);
        bc[j + 4] = __ldg(b1v + 64 + n0 + j);
    }
#pragma unroll
    for (int r = 0; r < 8; r++)
#pragma unroll
        for (int j = 0; j < 8; j++) x[r][j] += bc[j];

    // ---- rope: thread's 4-col group (4i..4i+3) holds full q/k rope pairs ----
    // q channels (2i,2i+1) = x cols (4i, 4i+2); k channels = x cols (4i+1, 4i+3)
#pragma unroll
    for (int r = 0; r < 8; r++) {
        int pos = pos0 + m0 + r;
        size_t rb = ((size_t)bidx * 512 + pos) * 64;
        {
            int i = tx;
            float s = g_sin[pos * 32 + i], c = g_cos[pos * 32 + i];
            float2 q = make_float2(x[r][0] * c - x[r][2] * s, x[r][0] * s + x[r][2] * c);
            float2 kk = make_float2(x[r][1] * c - x[r][3] * s, x[r][1] * s + x[r][3] * c);
            *(float2*)(g_qw + rb + 2 * i) = q;
            *(float2*)(g_kw + rb + 2 * i) = kk;
        }
        {
            int i = 16 + tx;
            float s = g_sin[pos * 32 + i], c = g_cos[pos * 32 + i];
            float2 q = make_float2(x[r][4] * c - x[r][6] * s, x[r][4] * s + x[r][6] * c);
            float2 kk = make_float2(x[r][5] * c - x[r][7] * s, x[r][5] * s + x[r][7] * c);
            *(float2*)(g_qw + rb + 2 * i) = q;
            *(float2*)(g_kw + rb + 2 * i) = kk;
        }
    }

    // ---- bias: x @ W2 + b2, /2 ----
    __syncthreads();
    float* xS  = sm;             // [64][132]
    float* w2t = sm + 64 * 132;  // [24][128] (W2 transposed)
#pragma unroll
    for (int r = 0; r < 8; r++) {
        *(float4*)(xS + (m0 + r) * 132 + n0)      = make_float4(x[r][0], x[r][1], x[r][2], x[r][3]);
        *(float4*)(xS + (m0 + r) * 132 + 64 + n0) = make_float4(x[r][4], x[r][5], x[r][6], x[r][7]);
    }
    for (int idx = t; idx < 3072; idx += 128) {
        int j = idx >> 7, k = idx & 127;
        w2t[j * 128 + k] = __ldg(W2 + k * 24 + j);
    }
    __syncthreads();

    for (int it = 0; it < 12; ++it) {
        int idx = t + it * 128;          // 1536 (j,m) pairs
        int j = idx >> 6, m = idx & 63;
        const float* xr = xS + m * 132;
        const float* wr = w2t + j * 128;
        float s = 0.f;
#pragma unroll
        for (int k = 0; k < 128; k += 4) {
            float4 xv = *(const float4*)(xr + k);
            float4 wv = *(const float4*)(wr + k);
            s += xv.x * wv.x + xv.y * wv.y + xv.z * wv.z + xv.w * wv.w;
        }
        s = (s + __ldg(b2v + j)) * 0.5f;
        int pos = pos0 + m;
        int h = j >> 1;
        float* dst = (j & 1) ? g_bk : g_bq;
        dst[((size_t)bidx * 12 + h) * 512 + pos] = s;
    }
}

// ================= K2: qk + per-head epilogue + masks =================
// Grid (8 n-tiles, 16 m-tiles, 16 batches), 256 threads.
// Tile: 32m x 64n; qk computed once, written for all 12 heads.
__global__ void __launch_bounds__(256) k2_out(const float* __restrict__ am,
                                              float* __restrict__ out)
{
    __shared__ __align__(16) float q_s[32 * 68];
    __shared__ __align__(16) float kT[64 * 64];
    __shared__ float bq_s[12 * 64];
    __shared__ float bk_s[12 * 32];
    __shared__ float amn_s[64];
    __shared__ float amm_s[32];

    int t = threadIdx.x;
    int b = blockIdx.z;
    int m0g = blockIdx.y * 32, n0g = blockIdx.x * 64;

#pragma unroll
    for (int i = 0; i < 2; i++) {
        int idx = t + i * 256;
        int row = idx >> 4, c = (idx & 15) << 2;
        *(float4*)(q_s + row * 68 + c) =
            *(const float4*)(g_qw + ((size_t)(b * 512 + m0g + row)) * 64 + c);
    }
    {
        int n = t & 63, kq = (t >> 6) << 4;
        const float* src = g_kw + ((size_t)(b * 512 + n0g + n)) * 64 + kq;
#pragma unroll
        for (int j = 0; j < 4; j++) {
            float4 v = *(const float4*)(src + j * 4);
            int kk = kq + j * 4;
            kT[(kk + 0) * 64 + n] = v.x;
            kT[(kk + 1) * 64 + n] = v.y;
            kT[(kk + 2) * 64 + n] = v.z;
            kT[(kk + 3) * 64 + n] = v.w;
        }
    }
    for (int idx = t; idx < 768; idx += 256) {
        int h = idx >> 6, n = idx & 63;
        bq_s[idx] = g_bq[((size_t)b * 12 + h) * 512 + n0g + n];
    }
    if (t < 384) {
        int h = t >> 5, m = t & 31;
        bk_s[t] = g_bk[((size_t)b * 12 + h) * 512 + m0g + m];
    }
    if (t < 64)       amn_s[t]      = am[b * 512 + n0g + t];
    else if (t < 96)  amm_s[t - 64] = am[b * 512 + m0g + (t - 64)];
    __syncthreads();

    int tx = t & 15, ty = t >> 4;
    int n0 = tx * 4, m0 = ty * 2;

    float4 acc0 = make_float4(0.f, 0.f, 0.f, 0.f);
    float4 acc1 = make_float4(0.f, 0.f, 0.f, 0.f);
#pragma unroll
    for (int k = 0; k < 64; k += 4) {
        float4 qa = *(const float4*)(q_s + m0 * 68 + k);
        float4 qb = *(const float4*)(q_s + (m0 + 1) * 68 + k);
        float4 k0v = *(const float4*)(kT + (k + 0) * 64 + n0);
        float4 k1v = *(const float4*)(kT + (k + 1) * 64 + n0);
        float4 k2v = *(const float4*)(kT + (k + 2) * 64 + n0);
        float4 k3v = *(const float4*)(kT + (k + 3) * 64 + n0);
        acc0.x += qa.x * k0v.x + qa.y * k1v.x + qa.z * k2v.x + qa.w * k3v.x;
        acc0.y += qa.x * k0v.y + qa.y * k1v.y + qa.z * k2v.y + qa.w * k3v.y;
        acc0.z += qa.x * k0v.z + qa.y * k1v.z + qa.z * k2v.z + qa.w * k3v.z;
        acc0.w += qa.x * k0v.w + qa.y * k1v.w + qa.z * k2v.w + qa.w * k3v.w;
        acc1.x += qb.x * k0v.x + qb.y * k1v.x + qb.z * k2v.x + qb.w * k3v.x;
        acc1.y += qb.x * k0v.y + qb.y * k1v.y + qb.z * k2v.y + qb.w * k3v.y;
        acc1.z += qb.x * k0v.z + qb.y * k1v.z + qb.z * k2v.z + qb.w * k3v.z;
        acc1.w += qb.x * k0v.w + qb.y * k1v.w + qb.z * k2v.w + qb.w * k3v.w;
    }
    float4 p0 = make_float4(acc0.x * 0.125f, acc0.y * 0.125f, acc0.z * 0.125f, acc0.w * 0.125f);
    float4 p1 = make_float4(acc1.x * 0.125f, acc1.y * 0.125f, acc1.z * 0.125f, acc1.w * 0.125f);

    float am_m0 = amm_s[m0], am_m1 = amm_s[m0 + 1];
    float4 amn4 = *(const float4*)(amn_s + n0);
    float4 at0 = make_float4((1.0f - amn4.x * am_m0) * INF_F, (1.0f - amn4.y * am_m0) * INF_F,
                             (1.0f - amn4.z * am_m0) * INF_F, (1.0f - amn4.w * am_m0) * INF_F);
    float4 at1 = make_float4((1.0f - amn4.x * am_m1) * INF_F, (1.0f - amn4.y * am_m1) * INF_F,
                             (1.0f - amn4.z * am_m1) * INF_F, (1.0f - amn4.w * am_m1) * INF_F);
    int gm0 = m0g + m0, gm1 = gm0 + 1;
    int gn = n0g + n0;
    float4 tr0 = make_float4((gn + 0 < gm0) ? INF_F : 0.f, (gn + 1 < gm0) ? INF_F : 0.f,
                             (gn + 2 < gm0) ? INF_F : 0.f, (gn + 3 < gm0) ? INF_F : 0.f);
    float4 tr1 = make_float4((gn + 0 < gm1) ? INF_F : 0.f, (gn + 1 < gm1) ? INF_F : 0.f,
                             (gn + 2 < gm1) ? INF_F : 0.f, (gn + 3 < gm1) ? INF_F : 0.f);

#pragma unroll
    for (int h = 0; h < 12; ++h) {
        float4 bqv = *(const float4*)(bq_s + h * 64 + n0);
        float bk0 = bk_s[h * 32 + m0], bk1 = bk_s[h * 32 + m0 + 1];
        float4 v0, v1;
        v0.x = ((p0.x + bqv.x) + bk0) - at0.x - tr0.x;
        v0.y = ((p0.y + bqv.y) + bk0) - at0.y - tr0.y;
        v0.z = ((p0.z + bqv.z) + bk0) - at0.z - tr0.z;
        v0.w = ((p0.w + bqv.w) + bk0) - at0.w - tr0.w;
        v1.x = ((p1.x + bqv.x) + bk1) - at1.x - tr1.x;
        v1.y = ((p1.y + bqv.y) + bk1) - at1.y - tr1.y;
        v1.z = ((p1.z + bqv.z) + bk1) - at1.z - tr1.z;
        v1.w = ((p1.w + bqv.w) + bk1) - at1.w - tr1.w;
        float* o = out + (((size_t)(b * 12 + h) * 512 + gm0) * 512 + gn);
        *(float4*)o = v0;
        *(float4*)(o + 512) = v1;
    }
}

// ================= launch =================
extern "C" void kernel_launch(void* const* d_in, const int* in_sizes, int n_in,
                              void* d_out, int out_size)
{
    const float* inp = (const float*)d_in[0];
    const float* am  = (const float*)d_in[1];
    const float* W1  = (const float*)d_in[2];
    const float* b1  = (const float*)d_in[3];
    const float* W2  = (const float*)d_in[4];
    const float* b2  = (const float*)d_in[5];
    float* out = (float*)d_out;

    k0_rope<<<64, 256>>>();
    k1_gemm<<<128, 128>>>(inp, W1, b1, W2, b2);
    k2_out<<<dim3(8, 16, 16), 256>>>(am, out);
}

// round 3
// speedup vs baseline: 1.0003x; 1.0003x over previous
#include <cuda_runtime.h>
#include <math.h>

#define INF_F 1000000000000.0f

typedef unsigned long long u64;

// ---------------- scratch (no cudaMalloc allowed) ----------------
__device__ float g_qw[16 * 512 * 64];    // rope'd q
__device__ float g_kw[16 * 512 * 64];    // rope'd k
__device__ float g_bq[16 * 12 * 512];    // bias[:,0::2]/2  (indexed by n)
__device__ float g_bk[16 * 12 * 512];    // bias[:,1::2]/2  (indexed by m)
__device__ float g_sin[512 * 32];
__device__ float g_cos[512 * 32];

// ---------------- f32x2 packed-FMA helpers (Blackwell FFMA2) ------
__device__ __forceinline__ u64 pk2(float lo, float hi) {
    u64 r; asm("mov.b64 %0,{%1,%2};" : "=l"(r) : "f"(lo), "f"(hi)); return r;
}
__device__ __forceinline__ void fma2(u64 &c, u64 a, u64 b) {
    asm("fma.rn.f32x2 %0,%1,%2,%0;" : "+l"(c) : "l"(a), "l"(b));
}
__device__ __forceinline__ float2 up2(u64 v) {
    float2 f; asm("mov.b64 {%0,%1},%2;" : "=f"(f.x), "=f"(f.y) : "l"(v)); return f;
}

// ================= K0: rope tables =================
__global__ void k0_rope() {
    int idx = blockIdx.x * 256 + threadIdx.x;
    if (idx < 512 * 32) {
        int pos = idx >> 5, i = idx & 31;
        float e = (float)(2 * i) * (1.0f / 64.0f);
        float invf = 1.0f / powf(10000.0f, e);
        float fr = (float)pos * invf;
        g_sin[idx] = sinf(fr);
        g_cos[idx] = cosf(fr);
    }
}

// ================= K1: x = inputs@W1+b1, rope split, bias =================
// Grid: 128 blocks (64 rows each of the 8192-row GEMM). 128 threads.
// Tile: BM=64, BN=128 (full), BK=16. Microtile 8m x 8n via FFMA2 (m-pairs).
__global__ void __launch_bounds__(128) k1_gemm(
    const float* __restrict__ inp, const float* __restrict__ W1,
    const float* __restrict__ b1v, const float* __restrict__ W2,
    const float* __restrict__ b2v)
{
    __shared__ __align__(16) float sm[11520];   // 46080 B, reused across phases
    float* aT = sm;              // [16][68]  (A transposed, padded)
    float* bS = sm + 16 * 68;    // [16][128]

    int t = threadIdx.x;
    int tx = t & 15, ty = t >> 4;        // 16 x 8 thread grid
    int row0 = blockIdx.x * 64;
    int bidx = row0 >> 9;
    int pos0 = row0 & 511;
    int m0 = ty * 8, n0 = tx * 4;

    u64 acc[4][8];
#pragma unroll
    for (int p = 0; p < 4; p++)
#pragma unroll
        for (int j = 0; j < 8; j++) acc[p][j] = 0ULL;

    float4 apre[2], bpre[4];

    // ---- load chunk 0 ----
#pragma unroll
    for (int i = 0; i < 2; i++) {
        int idx = t + i * 128; int m = idx >> 2; int kq = (idx & 3) << 2;
        apre[i] = *(const float4*)(inp + (size_t)(row0 + m) * 1024 + kq);
    }
#pragma unroll
    for (int i = 0; i < 4; i++) {
        int idx = t + i * 128; int k = idx >> 5; int n4 = (idx & 31) << 2;
        bpre[i] = *(const float4*)(W1 + (size_t)k * 128 + n4);
    }
#pragma unroll
    for (int i = 0; i < 2; i++) {
        int idx = t + i * 128; int m = idx >> 2; int kq = (idx & 3) << 2;
        aT[(kq + 0) * 68 + m] = apre[i].x;
        aT[(kq + 1) * 68 + m] = apre[i].y;
        aT[(kq + 2) * 68 + m] = apre[i].z;
        aT[(kq + 3) * 68 + m] = apre[i].w;
    }
#pragma unroll
    for (int i = 0; i < 4; i++) {
        int idx = t + i * 128; int k = idx >> 5; int n4 = (idx & 31) << 2;
        *(float4*)(bS + k * 128 + n4) = bpre[i];
    }
    __syncthreads();

    for (int kc = 0; kc < 64; ++kc) {
        if (kc < 63) {
            int kb = (kc + 1) * 16;
#pragma unroll
            for (int i = 0; i < 2; i++) {
                int idx = t + i * 128; int m = idx >> 2; int kq = (idx & 3) << 2;
                apre[i] = *(const float4*)(inp + (size_t)(row0 + m) * 1024 + kb + kq);
            }
#pragma unroll
            for (int i = 0; i < 4; i++) {
                int idx = t + i * 128; int k = idx >> 5; int n4 = (idx & 31) << 2;
                bpre[i] = *(const float4*)(W1 + (size_t)(kb + k) * 128 + n4);
            }
        }
#pragma unroll
        for (int k = 0; k < 16; k++) {
            float4 alo = *(const float4*)(aT + k * 68 + m0);
            float4 ahi = *(const float4*)(aT + k * 68 + m0 + 4);
            float4 bl  = *(const float4*)(bS + k * 128 + n0);
            float4 bh  = *(const float4*)(bS + k * 128 + 64 + n0);
            u64 ap[4];
            ap[0] = pk2(alo.x, alo.y); ap[1] = pk2(alo.z, alo.w);
            ap[2] = pk2(ahi.x, ahi.y); ap[3] = pk2(ahi.z, ahi.w);
            float bb[8] = {bl.x, bl.y, bl.z, bl.w, bh.x, bh.y, bh.z, bh.w};
#pragma unroll
            for (int j = 0; j < 8; j++) {
                u64 bd = pk2(bb[j], bb[j]);
#pragma unroll
                for (int p = 0; p < 4; p++) fma2(acc[p][j], ap[p], bd);
            }
        }
        __syncthreads();
        if (kc < 63) {
#pragma unroll
            for (int i = 0; i < 2; i++) {
                int idx = t + i * 128; int m = idx >> 2; int kq = (idx & 3) << 2;
                aT[(kq + 0) * 68 + m] = apre[i].x;
                aT[(kq + 1) * 68 + m] = apre[i].y;
                aT[(kq + 2) * 68 + m] = apre[i].z;
                aT[(kq + 3) * 68 + m] = apre[i].w;
            }
#pragma unroll
            for (int i = 0; i < 4; i++) {
                int idx = t + i * 128; int k = idx >> 5; int n4 = (idx & 31) << 2;
                *(float4*)(bS + k * 128 + n4) = bpre[i];
            }
            __syncthreads();
        }
    }

    // ---- epilogue: unpack + b1 ----
    float x[8][8];
#pragma unroll
    for (int p = 0; p < 4; p++)
#pragma unroll
        for (int j = 0; j < 8; j++) {
            float2 v = up2(acc[p][j]);
            x[2 * p][j] = v.x;
            x[2 * p + 1][j] = v.y;
        }
    float bc[8];
#pragma unroll
    for (int j = 0; j < 4; j++) {
        bc[j]     = __ldg(b1v + n0 + j);
        bc[j + 4] = __ldg(b1v + 64 + n0 + j);
    }
#pragma unroll
    for (int r = 0; r < 8; r++)
#pragma unroll
        for (int j = 0; j < 8; j++) x[r][j] += bc[j];

    // ---- rope: thread's 4-col group (4i..4i+3) holds full q/k rope pairs ----
    // q channels (2i,2i+1) = x cols (4i, 4i+2); k channels = x cols (4i+1, 4i+3)
#pragma unroll
    for (int r = 0; r < 8; r++) {
        int pos = pos0 + m0 + r;
        size_t rb = ((size_t)bidx * 512 + pos) * 64;
        {
            int i = tx;
            float s = g_sin[pos * 32 + i], c = g_cos[pos * 32 + i];
            float2 q = make_float2(x[r][0] * c - x[r][2] * s, x[r][0] * s + x[r][2] * c);
            float2 kk = make_float2(x[r][1] * c - x[r][3] * s, x[r][1] * s + x[r][3] * c);
            *(float2*)(g_qw + rb + 2 * i) = q;
            *(float2*)(g_kw + rb + 2 * i) = kk;
        }
        {
            int i = 16 + tx;
            float s = g_sin[pos * 32 + i], c = g_cos[pos * 32 + i];
            float2 q = make_float2(x[r][4] * c - x[r][6] * s, x[r][4] * s + x[r][6] * c);
            float2 kk = make_float2(x[r][5] * c - x[r][7] * s, x[r][5] * s + x[r][7] * c);
            *(float2*)(g_qw + rb + 2 * i) = q;
            *(float2*)(g_kw + rb + 2 * i) = kk;
        }
    }

    // ---- bias: x @ W2 + b2, /2 ----
    __syncthreads();
    float* xS  = sm;             // [64][132]
    float* w2t = sm + 64 * 132;  // [24][128] (W2 transposed)
#pragma unroll
    for (int r = 0; r < 8; r++) {
        *(float4*)(xS + (m0 + r) * 132 + n0)      = make_float4(x[r][0], x[r][1], x[r][2], x[r][3]);
        *(float4*)(xS + (m0 + r) * 132 + 64 + n0) = make_float4(x[r][4], x[r][5], x[r][6], x[r][7]);
    }
    for (int idx = t; idx < 3072; idx += 128) {
        int j = idx >> 7, k = idx & 127;
        w2t[j * 128 + k] = __ldg(W2 + k * 24 + j);
    }
    __syncthreads();

    for (int it = 0; it < 12; ++it) {
        int idx = t + it * 128;          // 1536 (j,m) pairs
        int j = idx >> 6, m = idx & 63;
        const float* xr = xS + m * 132;
        const float* wr = w2t + j * 128;
        float s = 0.f;
#pragma unroll
        for (int k = 0; k < 128; k += 4) {
            float4 xv = *(const float4*)(xr + k);
            float4 wv = *(const float4*)(wr + k);
            s += xv.x * wv.x + xv.y * wv.y + xv.z * wv.z + xv.w * wv.w;
        }
        s = (s + __ldg(b2v + j)) * 0.5f;
        int pos = pos0 + m;
        int h = j >> 1;
        float* dst = (j & 1) ? g_bk : g_bq;
        dst[((size_t)bidx * 12 + h) * 512 + pos] = s;
    }
}

// ================= K2: qk + per-head epilogue + masks =================
// Grid (8 n-tiles, 16 m-tiles, 16 batches), 256 threads.
// Tile: 32m x 64n; qk computed once, written for all 12 heads.
__global__ void __launch_bounds__(256) k2_out(const float* __restrict__ am,
                                              float* __restrict__ out)
{
    __shared__ __align__(16) float q_s[32 * 68];
    __shared__ __align__(16) float kT[64 * 64];
    __shared__ float bq_s[12 * 64];
    __shared__ float bk_s[12 * 32];
    __shared__ float amn_s[64];
    __shared__ float amm_s[32];

    int t = threadIdx.x;
    int b = blockIdx.z;
    int m0g = blockIdx.y * 32, n0g = blockIdx.x * 64;

#pragma unroll
    for (int i = 0; i < 2; i++) {
        int idx = t + i * 256;
        int row = idx >> 4, c = (idx & 15) << 2;
        *(float4*)(q_s + row * 68 + c) =
            *(const float4*)(g_qw + ((size_t)(b * 512 + m0g + row)) * 64 + c);
    }
    {
        int n = t & 63, kq = (t >> 6) << 4;
        const float* src = g_kw + ((size_t)(b * 512 + n0g + n)) * 64 + kq;
#pragma unroll
        for (int j = 0; j < 4; j++) {
            float4 v = *(const float4*)(src + j * 4);
            int kk = kq + j * 4;
            kT[(kk + 0) * 64 + n] = v.x;
            kT[(kk + 1) * 64 + n] = v.y;
            kT[(kk + 2) * 64 + n] = v.z;
            kT[(kk + 3) * 64 + n] = v.w;
        }
    }
    for (int idx = t; idx < 768; idx += 256) {
        int h = idx >> 6, n = idx & 63;
        bq_s[idx] = g_bq[((size_t)b * 12 + h) * 512 + n0g + n];
    }
    if (t < 384) {
        int h = t >> 5, m = t & 31;
        bk_s[t] = g_bk[((size_t)b * 12 + h) * 512 + m0g + m];
    }
    if (t < 64)       amn_s[t]      = am[b * 512 + n0g + t];
    else if (t < 96)  amm_s[t - 64] = am[b * 512 + m0g + (t - 64)];
    __syncthreads();

    int tx = t & 15, ty = t >> 4;
    int n0 = tx * 4, m0 = ty * 2;

    float4 acc0 = make_float4(0.f, 0.f, 0.f, 0.f);
    float4 acc1 = make_float4(0.f, 0.f, 0.f, 0.f);
#pragma unroll
    for (int k = 0; k < 64; k += 4) {
        float4 qa = *(const float4*)(q_s + m0 * 68 + k);
        float4 qb = *(const float4*)(q_s + (m0 + 1) * 68 + k);
        float4 k0v = *(const float4*)(kT + (k + 0) * 64 + n0);
        float4 k1v = *(const float4*)(kT + (k + 1) * 64 + n0);
        float4 k2v = *(const float4*)(kT + (k + 2) * 64 + n0);
        float4 k3v = *(const float4*)(kT + (k + 3) * 64 + n0);
        acc0.x += qa.x * k0v.x + qa.y * k1v.x + qa.z * k2v.x + qa.w * k3v.x;
        acc0.y += qa.x * k0v.y + qa.y * k1v.y + qa.z * k2v.y + qa.w * k3v.y;
        acc0.z += qa.x * k0v.z + qa.y * k1v.z + qa.z * k2v.z + qa.w * k3v.z;
        acc0.w += qa.x * k0v.w + qa.y * k1v.w + qa.z * k2v.w + qa.w * k3v.w;
        acc1.x += qb.x * k0v.x + qb.y * k1v.x + qb.z * k2v.x + qb.w * k3v.x;
        acc1.y += qb.x * k0v.y + qb.y * k1v.y + qb.z * k2v.y + qb.w * k3v.y;
        acc1.z += qb.x * k0v.z + qb.y * k1v.z + qb.z * k2v.z + qb.w * k3v.z;
        acc1.w += qb.x * k0v.w + qb.y * k1v.w + qb.z * k2v.w + qb.w * k3v.w;
    }
    float4 p0 = make_float4(acc0.x * 0.125f, acc0.y * 0.125f, acc0.z * 0.125f, acc0.w * 0.125f);
    float4 p1 = make_float4(acc1.x * 0.125f, acc1.y * 0.125f, acc1.z * 0.125f, acc1.w * 0.125f);

    float am_m0 = amm_s[m0], am_m1 = amm_s[m0 + 1];
    float4 amn4 = *(const float4*)(amn_s + n0);
    float4 at0 = make_float4((1.0f - amn4.x * am_m0) * INF_F, (1.0f - amn4.y * am_m0) * INF_F,
                             (1.0f - amn4.z * am_m0) * INF_F, (1.0f - amn4.w * am_m0) * INF_F);
    float4 at1 = make_float4((1.0f - amn4.x * am_m1) * INF_F, (1.0f - amn4.y * am_m1) * INF_F,
                             (1.0f - amn4.z * am_m1) * INF_F, (1.0f - amn4.w * am_m1) * INF_F);
    int gm0 = m0g + m0, gm1 = gm0 + 1;
    int gn = n0g + n0;
    float4 tr0 = make_float4((gn + 0 < gm0) ? INF_F : 0.f, (gn + 1 < gm0) ? INF_F : 0.f,
                             (gn + 2 < gm0) ? INF_F : 0.f, (gn + 3 < gm0) ? INF_F : 0.f);
    float4 tr1 = make_float4((gn + 0 < gm1) ? INF_F : 0.f, (gn + 1 < gm1) ? INF_F : 0.f,
                             (gn + 2 < gm1) ? INF_F : 0.f, (gn + 3 < gm1) ? INF_F : 0.f);

#pragma unroll
    for (int h = 0; h < 12; ++h) {
        float4 bqv = *(const float4*)(bq_s + h * 64 + n0);
        float bk0 = bk_s[h * 32 + m0], bk1 = bk_s[h * 32 + m0 + 1];
        float4 v0, v1;
        v0.x = ((p0.x + bqv.x) + bk0) - at0.x - tr0.x;
        v0.y = ((p0.y + bqv.y) + bk0) - at0.y - tr0.y;
        v0.z = ((p0.z + bqv.z) + bk0) - at0.z - tr0.z;
        v0.w = ((p0.w + bqv.w) + bk0) - at0.w - tr0.w;
        v1.x = ((p1.x + bqv.x) + bk1) - at1.x - tr1.x;
        v1.y = ((p1.y + bqv.y) + bk1) - at1.y - tr1.y;
        v1.z = ((p1.z + bqv.z) + bk1) - at1.z - tr1.z;
        v1.w = ((p1.w + bqv.w) + bk1) - at1.w - tr1.w;
        float* o = out + (((size_t)(b * 12 + h) * 512 + gm0) * 512 + gn);
        *(float4*)o = v0;
        *(float4*)(o + 512) = v1;
    }
}

// ================= launch =================
extern "C" void kernel_launch(void* const* d_in, const int* in_sizes, int n_in,
                              void* d_out, int out_size)
{
    const float* inp = (const float*)d_in[0];
    const float* am  = (const float*)d_in[1];
    const float* W1  = (const float*)d_in[2];
    const float* b1  = (const float*)d_in[3];
    const float* W2  = (const float*)d_in[4];
    const float* b2  = (const float*)d_in[5];
    float* out = (float*)d_out;

    k0_rope<<<64, 256>>>();
    k1_gemm<<<128, 128>>>(inp, W1, b1, W2, b2);
    k2_out<<<dim3(8, 16, 16), 256>>>(am, out);
}

// round 5
// speedup vs baseline: 1.0672x; 1.0670x over previous
#include <cuda_runtime.h>
#include <math.h>

#define INF_F 1000000000000.0f

typedef unsigned long long u64;

// ---------------- scratch (no cudaMalloc allowed) ----------------
__device__ float g_qw[16 * 512 * 64];    // rope'd q
__device__ float g_kw[16 * 512 * 64];    // rope'd k
__device__ float g_bq[16 * 12 * 512];    // bias[:,0::2]/2  (indexed by n)
__device__ float g_bk[16 * 12 * 512];    // bias[:,1::2]/2  (indexed by m)
__device__ float g_sin[512 * 32];
__device__ float g_cos[512 * 32];

// ---------------- f32x2 packed helpers (Blackwell FFMA2) ----------
__device__ __forceinline__ u64 pk2(float lo, float hi) {
    u64 r; asm("mov.b64 %0,{%1,%2};" : "=l"(r) : "f"(lo), "f"(hi)); return r;
}
__device__ __forceinline__ void fma2(u64 &c, u64 a, u64 b) {
    asm("fma.rn.f32x2 %0,%1,%2,%0;" : "+l"(c) : "l"(a), "l"(b));
}
__device__ __forceinline__ u64 add2(u64 a, u64 b) {
    u64 d; asm("add.rn.f32x2 %0,%1,%2;" : "=l"(d) : "l"(a), "l"(b)); return d;
}
__device__ __forceinline__ float2 up2(u64 v) {
    float2 f; asm("mov.b64 {%0,%1},%2;" : "=f"(f.x), "=f"(f.y) : "l"(v)); return f;
}

// ================= K0: rope tables =================
__global__ void k0_rope() {
    int idx = blockIdx.x * 256 + threadIdx.x;
    if (idx < 512 * 32) {
        int pos = idx >> 5, i = idx & 31;
        float e = (float)(2 * i) * (1.0f / 64.0f);
        float invf = 1.0f / powf(10000.0f, e);
        float fr = (float)pos * invf;
        float s, c;
        sincosf(fr, &s, &c);
        g_sin[idx] = s;
        g_cos[idx] = c;
    }
}

// ================= K1: x = inputs@W1+b1, rope split, bias =================
// Grid: 256 blocks (BM=32 rows each), 128 threads, BN=128 (full), BK=16.
// Microtile 4m x 8n via FFMA2 on m-pairs. Double-buffered smem (1 sync/chunk).
__global__ void __launch_bounds__(128) k1_gemm(
    const float* __restrict__ inp, const float* __restrict__ W1,
    const float* __restrict__ b1v, const float* __restrict__ W2,
    const float* __restrict__ b2v)
{
    __shared__ __align__(16) float sm[7296];
    // main loop: 2 buffers of (A[16][36] = 576) + (B[16][128] = 2048) = 2624 fl
    // epilogue reuse: xS[32][132]=4224 + w2t[24][128]=3072 = 7296 fl

    int t = threadIdx.x;
    int tx = t & 15, ty = t >> 4;        // 16 x 8 thread grid
    int row0 = blockIdx.x * 32;
    int bidx = row0 >> 9;
    int pos0 = row0 & 511;
    int m0 = ty * 4, n0 = tx * 4;

    // global-load index precompute
    int am_ = t >> 2;                    // A: row within tile (0..31)
    int akq = (t & 3) << 2;              // A: k quad within chunk

    u64 acc[2][8];
#pragma unroll
    for (int p = 0; p < 2; p++)
#pragma unroll
        for (int j = 0; j < 8; j++) acc[p][j] = 0ULL;

    float4 apre, bpre[4];
    const float* arow = inp + (size_t)(row0 + am_) * 1024 + akq;

    // ---- load chunk 0 into buffer 0 ----
    apre = *(const float4*)(arow);
#pragma unroll
    for (int i = 0; i < 4; i++) {
        int idx = t + i * 128; int k = idx >> 5; int n4 = (idx & 31) << 2;
        bpre[i] = *(const float4*)(W1 + (size_t)k * 128 + n4);
    }
    {
        float* aT = sm;
        float* bS = sm + 576;
        aT[(akq + 0) * 36 + am_] = apre.x;
        aT[(akq + 1) * 36 + am_] = apre.y;
        aT[(akq + 2) * 36 + am_] = apre.z;
        aT[(akq + 3) * 36 + am_] = apre.w;
#pragma unroll
        for (int i = 0; i < 4; i++) {
            int idx = t + i * 128; int k = idx >> 5; int n4 = (idx & 31) << 2;
            *(float4*)(bS + k * 128 + n4) = bpre[i];
        }
    }
    __syncthreads();

    for (int kc = 0; kc < 64; ++kc) {
        if (kc < 63) {
            int kb = (kc + 1) * 16;
            apre = *(const float4*)(arow + kb);
#pragma unroll
            for (int i = 0; i < 4; i++) {
                int idx = t + i * 128; int k = idx >> 5; int n4 = (idx & 31) << 2;
                bpre[i] = *(const float4*)(W1 + (size_t)(kb + k) * 128 + n4);
            }
        }
        const float* aT = sm + (kc & 1) * 2624;
        const float* bS = aT + 576;
#pragma unroll
        for (int k = 0; k < 16; k++) {
            float4 a  = *(const float4*)(aT + k * 36 + m0);
            float4 bl = *(const float4*)(bS + k * 128 + n0);
            float4 bh = *(const float4*)(bS + k * 128 + 64 + n0);
            u64 ap0 = pk2(a.x, a.y);
            u64 ap1 = pk2(a.z, a.w);
            float bb[8] = {bl.x, bl.y, bl.z, bl.w, bh.x, bh.y, bh.z, bh.w};
#pragma unroll
            for (int j = 0; j < 8; j++) {
                u64 bd = pk2(bb[j], bb[j]);
                fma2(acc[0][j], ap0, bd);
                fma2(acc[1][j], ap1, bd);
            }
        }
        if (kc < 63) {
            float* aTn = sm + ((kc + 1) & 1) * 2624;
            float* bSn = aTn + 576;
            aTn[(akq + 0) * 36 + am_] = apre.x;
            aTn[(akq + 1) * 36 + am_] = apre.y;
            aTn[(akq + 2) * 36 + am_] = apre.z;
            aTn[(akq + 3) * 36 + am_] = apre.w;
#pragma unroll
            for (int i = 0; i < 4; i++) {
                int idx = t + i * 128; int k = idx >> 5; int n4 = (idx & 31) << 2;
                *(float4*)(bSn + k * 128 + n4) = bpre[i];
            }
            __syncthreads();
        }
    }

    // ---- epilogue: unpack + b1 ----
    float x[4][8];
#pragma unroll
    for (int p = 0; p < 2; p++)
#pragma unroll
        for (int j = 0; j < 8; j++) {
            float2 v = up2(acc[p][j]);
            x[2 * p][j] = v.x;
            x[2 * p + 1][j] = v.y;
        }
    float bc[8];
#pragma unroll
    for (int j = 0; j < 4; j++) {
        bc[j]     = __ldg(b1v + n0 + j);
        bc[j + 4] = __ldg(b1v + 64 + n0 + j);
    }
#pragma unroll
    for (int r = 0; r < 4; r++)
#pragma unroll
        for (int j = 0; j < 8; j++) x[r][j] += bc[j];

    // ---- rope: cols (4tx..4tx+3) hold full q/k rope pairs for i=tx; +64 for i=16+tx
#pragma unroll
    for (int r = 0; r < 4; r++) {
        int pos = pos0 + m0 + r;
        size_t rb = ((size_t)bidx * 512 + pos) * 64;
        {
            int i = tx;
            float s = g_sin[pos * 32 + i], c = g_cos[pos * 32 + i];
            float2 q = make_float2(x[r][0] * c - x[r][2] * s, x[r][0] * s + x[r][2] * c);
            float2 kk = make_float2(x[r][1] * c - x[r][3] * s, x[r][1] * s + x[r][3] * c);
            *(float2*)(g_qw + rb + 2 * i) = q;
            *(float2*)(g_kw + rb + 2 * i) = kk;
        }
        {
            int i = 16 + tx;
            float s = g_sin[pos * 32 + i], c = g_cos[pos * 32 + i];
            float2 q = make_float2(x[r][4] * c - x[r][6] * s, x[r][4] * s + x[r][6] * c);
            float2 kk = make_float2(x[r][5] * c - x[r][7] * s, x[r][5] * s + x[r][7] * c);
            *(float2*)(g_qw + rb + 2 * i) = q;
            *(float2*)(g_kw + rb + 2 * i) = kk;
        }
    }

    // ---- bias: x @ W2 + b2, /2 ----
    __syncthreads();
    float* xS  = sm;             // [32][132]
    float* w2t = sm + 32 * 132;  // [24][128]
#pragma unroll
    for (int r = 0; r < 4; r++) {
        *(float4*)(xS + (m0 + r) * 132 + n0)      = make_float4(x[r][0], x[r][1], x[r][2], x[r][3]);
        *(float4*)(xS + (m0 + r) * 132 + 64 + n0) = make_float4(x[r][4], x[r][5], x[r][6], x[r][7]);
    }
    for (int idx = t; idx < 3072; idx += 128) {
        int j = idx >> 7, k = idx & 127;
        w2t[j * 128 + k] = __ldg(W2 + k * 24 + j);
    }
    __syncthreads();

#pragma unroll
    for (int it = 0; it < 6; ++it) {
        int idx = t + it * 128;          // 768 (j,m) pairs
        int j = idx >> 5, m = idx & 31;
        const float* xr = xS + m * 132;
        const float* wr = w2t + j * 128;
        float s = 0.f;
#pragma unroll
        for (int k = 0; k < 128; k += 4) {
            float4 xv = *(const float4*)(xr + k);
            float4 wv = *(const float4*)(wr + k);
            s += xv.x * wv.x + xv.y * wv.y + xv.z * wv.z + xv.w * wv.w;
        }
        s = (s + __ldg(b2v + j)) * 0.5f;
        int pos = pos0 + m;
        int h = j >> 1;
        float* dst = (j & 1) ? g_bk : g_bq;
        dst[((size_t)bidx * 12 + h) * 512 + pos] = s;
    }
}

// ================= K2: qk + per-head epilogue + masks =================
// Grid (8 n-tiles, 16 m-tiles, 16 batches), 256 threads.
// Tile: 32m x 64n; qk computed once (f32x2), fanned out to all 12 heads.
__global__ void __launch_bounds__(256) k2_out(const float* __restrict__ am,
                                              float* __restrict__ out)
{
    __shared__ __align__(16) float q_s[32 * 68];
    __shared__ __align__(16) float kT[64 * 64];
    __shared__ __align__(16) float bq_s[12 * 64];
    __shared__ float bk_s[12 * 32];
    __shared__ float amn_s[64];
    __shared__ float amm_s[32];

    int t = threadIdx.x;
    int b = blockIdx.z;
    int m0g = blockIdx.y * 32, n0g = blockIdx.x * 64;

#pragma unroll
    for (int i = 0; i < 2; i++) {
        int idx = t + i * 256;
        int row = idx >> 4, c = (idx & 15) << 2;
        *(float4*)(q_s + row * 68 + c) =
            *(const float4*)(g_qw + ((size_t)(b * 512 + m0g + row)) * 64 + c);
    }
    {
        int n = t & 63, kq = (t >> 6) << 4;
        const float* src = g_kw + ((size_t)(b * 512 + n0g + n)) * 64 + kq;
#pragma unroll
        for (int j = 0; j < 4; j++) {
            float4 v = *(const float4*)(src + j * 4);
            int kk = kq + j * 4;
            kT[(kk + 0) * 64 + n] = v.x;
            kT[(kk + 1) * 64 + n] = v.y;
            kT[(kk + 2) * 64 + n] = v.z;
            kT[(kk + 3) * 64 + n] = v.w;
        }
    }
    for (int idx = t; idx < 768; idx += 256) {
        int h = idx >> 6, n = idx & 63;
        bq_s[idx] = g_bq[((size_t)b * 12 + h) * 512 + n0g + n];
    }
    if (t < 384) {
        int h = t >> 5, m = t & 31;
        bk_s[t] = g_bk[((size_t)b * 12 + h) * 512 + m0g + m];
    }
    if (t < 64)       amn_s[t]      = am[b * 512 + n0g + t];
    else if (t < 96)  amm_s[t - 64] = am[b * 512 + m0g + (t - 64)];
    __syncthreads();

    int tx = t & 15, ty = t >> 4;
    int n0 = tx * 4, m0 = ty * 2;

    // f32x2 qk accumulation: acc[m][npair]
    u64 a00 = 0ULL, a01 = 0ULL, a10 = 0ULL, a11 = 0ULL;
#pragma unroll
    for (int k = 0; k < 64; k += 4) {
        float4 qa = *(const float4*)(q_s + m0 * 68 + k);
        float4 qb = *(const float4*)(q_s + (m0 + 1) * 68 + k);
#pragma unroll
        for (int kk = 0; kk < 4; kk++) {
            const u64* kv = (const u64*)(kT + (k + kk) * 64 + n0);
            u64 k01 = kv[0], k23 = kv[1];
            float qav = (kk == 0) ? qa.x : (kk == 1) ? qa.y : (kk == 2) ? qa.z : qa.w;
            float qbv = (kk == 0) ? qb.x : (kk == 1) ? qb.y : (kk == 2) ? qb.z : qb.w;
            u64 qap = pk2(qav, qav);
            u64 qbp = pk2(qbv, qbv);
            fma2(a00, k01, qap);
            fma2(a01, k23, qap);
            fma2(a10, k01, qbp);
            fma2(a11, k23, qbp);
        }
    }
    float2 v00 = up2(a00), v01 = up2(a01), v10 = up2(a10), v11 = up2(a11);
    float p0[4] = {v00.x, v00.y, v01.x, v01.y};
    float p1[4] = {v10.x, v10.y, v11.x, v11.y};

    float am_m0 = amm_s[m0], am_m1 = amm_s[m0 + 1];
    float4 amn4 = *(const float4*)(amn_s + n0);
    float amn[4] = {amn4.x, amn4.y, amn4.z, amn4.w};
    int gm0 = m0g + m0, gm1 = gm0 + 1;
    int gn = n0g + n0;

    // pre = qk*0.125 - at - tr   (hoisted out of head loop; exact vs ref)
    float pre0[4], pre1[4];
#pragma unroll
    for (int j = 0; j < 4; j++) {
        float at0 = (1.0f - amn[j] * am_m0) * INF_F;
        float at1 = (1.0f - amn[j] * am_m1) * INF_F;
        float tr0 = (gn + j < gm0) ? INF_F : 0.f;
        float tr1 = (gn + j < gm1) ? INF_F : 0.f;
        pre0[j] = p0[j] * 0.125f - at0 - tr0;
        pre1[j] = p1[j] * 0.125f - at1 - tr1;
    }
    u64 pre0a = pk2(pre0[0], pre0[1]), pre0b = pk2(pre0[2], pre0[3]);
    u64 pre1a = pk2(pre1[0], pre1[1]), pre1b = pk2(pre1[2], pre1[3]);

    float* obase = out + (((size_t)b * 12 * 512 + gm0) * 512 + gn);
#pragma unroll
    for (int h = 0; h < 12; ++h) {
        const u64* bqp = (const u64*)(bq_s + h * 64 + n0);
        u64 bqa = bqp[0], bqb = bqp[1];
        float bk0 = bk_s[h * 32 + m0], bk1 = bk_s[h * 32 + m0 + 1];
        u64 bk0p = pk2(bk0, bk0), bk1p = pk2(bk1, bk1);

        u64 w0a = add2(add2(pre0a, bqa), bk0p);
        u64 w0b = add2(add2(pre0b, bqb), bk0p);
        u64 w1a = add2(add2(pre1a, bqa), bk1p);
        u64 w1b = add2(add2(pre1b, bqb), bk1p);

        float2 l0 = up2(w0a), h0 = up2(w0b);
        float2 l1 = up2(w1a), h1 = up2(w1b);
        float* o = obase + (size_t)h * 512 * 512;
        __stcs((float4*)o,         make_float4(l0.x, l0.y, h0.x, h0.y));
        __stcs((float4*)(o + 512), make_float4(l1.x, l1.y, h1.x, h1.y));
    }
}

// ================= launch =================
extern "C" void kernel_launch(void* const* d_in, const int* in_sizes, int n_in,
                              void* d_out, int out_size)
{
    const float* inp = (const float*)d_in[0];
    const float* am  = (const float*)d_in[1];
    const float* W1  = (const float*)d_in[2];
    const float* b1  = (const float*)d_in[3];
    const float* W2  = (const float*)d_in[4];
    const float* b2  = (const float*)d_in[5];
    float* out = (float*)d_out;

    k0_rope<<<64, 256>>>();
    k1_gemm<<<256, 128>>>(inp, W1, b1, W2, b2);
    k2_out<<<dim3(8, 16, 16), 256>>>(am, out);
}

// round 6
// speedup vs baseline: 1.1109x; 1.0409x over previous
#include <cuda_runtime.h>
#include <math.h>

#define INF_F 1000000000000.0f

typedef unsigned long long u64;

// ---------------- scratch (no cudaMalloc allowed) ----------------
__device__ float g_qw[16 * 512 * 64];    // rope'd q
__device__ float g_kw[16 * 512 * 64];    // rope'd k
__device__ float g_bq[16 * 12 * 512];    // bias[:,0::2]/2  (indexed by n)
__device__ float g_bk[16 * 12 * 512];    // bias[:,1::2]/2  (indexed by m)

// ---------------- f32x2 packed helpers (Blackwell FFMA2) ----------
__device__ __forceinline__ u64 pk2(float lo, float hi) {
    u64 r; asm("mov.b64 %0,{%1,%2};" : "=l"(r) : "f"(lo), "f"(hi)); return r;
}
__device__ __forceinline__ void fma2(u64 &c, u64 a, u64 b) {
    asm("fma.rn.f32x2 %0,%1,%2,%0;" : "+l"(c) : "l"(a), "l"(b));
}
__device__ __forceinline__ u64 add2(u64 a, u64 b) {
    u64 d; asm("add.rn.f32x2 %0,%1,%2;" : "=l"(d) : "l"(a), "l"(b)); return d;
}
__device__ __forceinline__ float2 up2(u64 v) {
    float2 f; asm("mov.b64 {%0,%1},%2;" : "=f"(f.x), "=f"(f.y) : "l"(v)); return f;
}

// ================= K1: x = inputs@W1+b1, rope split, bias =================
// Grid: 256 blocks (BM=32 rows each), 128 threads, BN=128 (full), BK=16.
// Microtile 4m x 8n via FFMA2 on n-pairs (b loaded as u64 directly from smem,
// a broadcast-packed: 4 MOVs per k-step instead of 10).
// Double-buffered smem (1 sync/chunk). Rope sin/cos table computed per-block
// into spare smem, overlapped with the first chunk's global loads.
__global__ void __launch_bounds__(128) k1_gemm(
    const float* __restrict__ inp, const float* __restrict__ W1,
    const float* __restrict__ b1v, const float* __restrict__ W2,
    const float* __restrict__ b2v)
{
    __shared__ __align__(16) float sm[7296];
    // main loop: 2 x (A[16][36]=576 + B[16][128]=2048) = 5248 fl
    // sin/cos table: [5248..7296) = 1024+1024 fl (local pos 0..31 x i 0..31)
    // epilogue reuse: xS[32][132]=4224 + w2t[24][128]=3072 = 7296 fl
    float* sinS = sm + 5248;
    float* cosS = sm + 6272;

    int t = threadIdx.x;
    int tx = t & 15, ty = t >> 4;        // 16 x 8 thread grid
    int row0 = blockIdx.x * 32;
    int bidx = row0 >> 9;
    int pos0 = row0 & 511;
    int m0 = ty * 4, n0 = tx * 4;

    int am_ = t >> 2;                    // A: row within tile (0..31)
    int akq = (t & 3) << 2;              // A: k quad within chunk

    u64 acc[4][4];                       // [m][npair]
#pragma unroll
    for (int p = 0; p < 4; p++)
#pragma unroll
        for (int j = 0; j < 4; j++) acc[p][j] = 0ULL;

    float4 apre, bpre[4];
    const float* arow = inp + (size_t)(row0 + am_) * 1024 + akq;

    // ---- issue chunk-0 global loads first (latency cover for sincos below)
    apre = *(const float4*)(arow);
#pragma unroll
    for (int i = 0; i < 4; i++) {
        int idx = t + i * 128; int k = idx >> 5; int n4 = (idx & 31) << 2;
        bpre[i] = *(const float4*)(W1 + (size_t)k * 128 + n4);
    }

    // ---- rope tables for this block's 32 positions (exact: powf + sincosf)
    {
        int i = t & 31;                  // rope channel 0..31
        int pr0 = (t >> 5) * 8;          // 8 local positions per thread
        float e = (float)(2 * i) * (1.0f / 64.0f);
        float invf = 1.0f / powf(10000.0f, e);
#pragma unroll
        for (int r = 0; r < 8; r++) {
            int pl = pr0 + r;
            float fr = (float)(pos0 + pl) * invf;
            float s, c;
            sincosf(fr, &s, &c);
            sinS[pl * 32 + i] = s;
            cosS[pl * 32 + i] = c;
        }
    }

    {
        float* aT = sm;
        float* bS = sm + 576;
        aT[(akq + 0) * 36 + am_] = apre.x;
        aT[(akq + 1) * 36 + am_] = apre.y;
        aT[(akq + 2) * 36 + am_] = apre.z;
        aT[(akq + 3) * 36 + am_] = apre.w;
#pragma unroll
        for (int i = 0; i < 4; i++) {
            int idx = t + i * 128; int k = idx >> 5; int n4 = (idx & 31) << 2;
            *(float4*)(bS + k * 128 + n4) = bpre[i];
        }
    }
    __syncthreads();

    for (int kc = 0; kc < 64; ++kc) {
        if (kc < 63) {
            int kb = (kc + 1) * 16;
            apre = *(const float4*)(arow + kb);
#pragma unroll
            for (int i = 0; i < 4; i++) {
                int idx = t + i * 128; int k = idx >> 5; int n4 = (idx & 31) << 2;
                bpre[i] = *(const float4*)(W1 + (size_t)(kb + k) * 128 + n4);
            }
        }
        const float* aT = sm + (kc & 1) * 2624;
        const float* bS = aT + 576;
#pragma unroll
        for (int k = 0; k < 16; k++) {
            float4 a = *(const float4*)(aT + k * 36 + m0);
            const u64* bl = (const u64*)(bS + k * 128 + n0);
            const u64* bh = (const u64*)(bS + k * 128 + 64 + n0);
            u64 b0 = bl[0], b1 = bl[1], b2 = bh[0], b3 = bh[1];
            u64 a0 = pk2(a.x, a.x), a1 = pk2(a.y, a.y);
            u64 a2 = pk2(a.z, a.z), a3 = pk2(a.w, a.w);
            fma2(acc[0][0], a0, b0); fma2(acc[0][1], a0, b1);
            fma2(acc[0][2], a0, b2); fma2(acc[0][3], a0, b3);
            fma2(acc[1][0], a1, b0); fma2(acc[1][1], a1, b1);
            fma2(acc[1][2], a1, b2); fma2(acc[1][3], a1, b3);
            fma2(acc[2][0], a2, b0); fma2(acc[2][1], a2, b1);
            fma2(acc[2][2], a2, b2); fma2(acc[2][3], a2, b3);
            fma2(acc[3][0], a3, b0); fma2(acc[3][1], a3, b1);
            fma2(acc[3][2], a3, b2); fma2(acc[3][3], a3, b3);
        }
        if (kc < 63) {
            float* aTn = sm + ((kc + 1) & 1) * 2624;
            float* bSn = aTn + 576;
            aTn[(akq + 0) * 36 + am_] = apre.x;
            aTn[(akq + 1) * 36 + am_] = apre.y;
            aTn[(akq + 2) * 36 + am_] = apre.z;
            aTn[(akq + 3) * 36 + am_] = apre.w;
#pragma unroll
            for (int i = 0; i < 4; i++) {
                int idx = t + i * 128; int k = idx >> 5; int n4 = (idx & 31) << 2;
                *(float4*)(bSn + k * 128 + n4) = bpre[i];
            }
            __syncthreads();
        }
    }

    // ---- epilogue: unpack + b1 ----
    // acc[r][j] lanes: j=0,1 -> cols n0+0..3 ; j=2,3 -> cols 64+n0+0..3
    float x[4][8];
#pragma unroll
    for (int r = 0; r < 4; r++)
#pragma unroll
        for (int j = 0; j < 4; j++) {
            float2 v = up2(acc[r][j]);
            x[r][2 * j]     = v.x;
            x[r][2 * j + 1] = v.y;
        }
    float bc[8];
#pragma unroll
    for (int j = 0; j < 4; j++) {
        bc[j]     = __ldg(b1v + n0 + j);
        bc[j + 4] = __ldg(b1v + 64 + n0 + j);
    }
#pragma unroll
    for (int r = 0; r < 4; r++)
#pragma unroll
        for (int j = 0; j < 8; j++) x[r][j] += bc[j];

    // ---- rope: cols (4tx..4tx+3) hold full q/k rope pairs for i=tx; +64 for i=16+tx
#pragma unroll
    for (int r = 0; r < 4; r++) {
        int pl = m0 + r;                 // local position 0..31
        int pos = pos0 + pl;
        size_t rb = ((size_t)bidx * 512 + pos) * 64;
        {
            int i = tx;
            float s = sinS[pl * 32 + i], c = cosS[pl * 32 + i];
            float2 q = make_float2(x[r][0] * c - x[r][2] * s, x[r][0] * s + x[r][2] * c);
            float2 kk = make_float2(x[r][1] * c - x[r][3] * s, x[r][1] * s + x[r][3] * c);
            *(float2*)(g_qw + rb + 2 * i) = q;
            *(float2*)(g_kw + rb + 2 * i) = kk;
        }
        {
            int i = 16 + tx;
            float s = sinS[pl * 32 + i], c = cosS[pl * 32 + i];
            float2 q = make_float2(x[r][4] * c - x[r][6] * s, x[r][4] * s + x[r][6] * c);
            float2 kk = make_float2(x[r][5] * c - x[r][7] * s, x[r][5] * s + x[r][7] * c);
            *(float2*)(g_qw + rb + 2 * i) = q;
            *(float2*)(g_kw + rb + 2 * i) = kk;
        }
    }

    // ---- bias: x @ W2 + b2, /2 ----
    __syncthreads();
    float* xS  = sm;             // [32][132]
    float* w2t = sm + 32 * 132;  // [24][128]  (overwrites sin/cos table - done)
#pragma unroll
    for (int r = 0; r < 4; r++) {
        *(float4*)(xS + (m0 + r) * 132 + n0)      = make_float4(x[r][0], x[r][1], x[r][2], x[r][3]);
        *(float4*)(xS + (m0 + r) * 132 + 64 + n0) = make_float4(x[r][4], x[r][5], x[r][6], x[r][7]);
    }
    for (int idx = t; idx < 3072; idx += 128) {
        int j = idx >> 7, k = idx & 127;
        w2t[j * 128 + k] = __ldg(W2 + k * 24 + j);
    }
    __syncthreads();

#pragma unroll
    for (int it = 0; it < 6; ++it) {
        int idx = t + it * 128;          // 768 (j,m) pairs
        int j = idx >> 5, m = idx & 31;
        const float* xr = xS + m * 132;
        const float* wr = w2t + j * 128;
        float s = 0.f;
#pragma unroll
        for (int k = 0; k < 128; k += 4) {
            float4 xv = *(const float4*)(xr + k);
            float4 wv = *(const float4*)(wr + k);
            s += xv.x * wv.x + xv.y * wv.y + xv.z * wv.z + xv.w * wv.w;
        }
        s = (s + __ldg(b2v + j)) * 0.5f;
        int pos = pos0 + m;
        int h = j >> 1;
        float* dst = (j & 1) ? g_bk : g_bq;
        dst[((size_t)bidx * 12 + h) * 512 + pos] = s;
    }
}

// ================= K2: qk + per-head epilogue + masks =================
// Grid (8 n-tiles, 16 m-tiles, 16 batches), 256 threads.
// Tile: 32m x 64n; qk computed once (f32x2), fanned out to all 12 heads.
__global__ void __launch_bounds__(256) k2_out(const float* __restrict__ am,
                                              float* __restrict__ out)
{
    __shared__ __align__(16) float q_s[32 * 68];
    __shared__ __align__(16) float kT[64 * 64];
    __shared__ __align__(16) float bq_s[12 * 64];
    __shared__ float bk_s[12 * 32];
    __shared__ float amn_s[64];
    __shared__ float amm_s[32];

    int t = threadIdx.x;
    int b = blockIdx.z;
    int m0g = blockIdx.y * 32, n0g = blockIdx.x * 64;

#pragma unroll
    for (int i = 0; i < 2; i++) {
        int idx = t + i * 256;
        int row = idx >> 4, c = (idx & 15) << 2;
        *(float4*)(q_s + row * 68 + c) =
            *(const float4*)(g_qw + ((size_t)(b * 512 + m0g + row)) * 64 + c);
    }
    {
        int n = t & 63, kq = (t >> 6) << 4;
        const float* src = g_kw + ((size_t)(b * 512 + n0g + n)) * 64 + kq;
#pragma unroll
        for (int j = 0; j < 4; j++) {
            float4 v = *(const float4*)(src + j * 4);
            int kk = kq + j * 4;
            kT[(kk + 0) * 64 + n] = v.x;
            kT[(kk + 1) * 64 + n] = v.y;
            kT[(kk + 2) * 64 + n] = v.z;
            kT[(kk + 3) * 64 + n] = v.w;
        }
    }
    for (int idx = t; idx < 768; idx += 256) {
        int h = idx >> 6, n = idx & 63;
        bq_s[idx] = g_bq[((size_t)b * 12 + h) * 512 + n0g + n];
    }
    if (t < 384) {
        int h = t >> 5, m = t & 31;
        bk_s[t] = g_bk[((size_t)b * 12 + h) * 512 + m0g + m];
    }
    if (t < 64)       amn_s[t]      = am[b * 512 + n0g + t];
    else if (t < 96)  amm_s[t - 64] = am[b * 512 + m0g + (t - 64)];
    __syncthreads();

    int tx = t & 15, ty = t >> 4;
    int n0 = tx * 4, m0 = ty * 2;

    // f32x2 qk accumulation: acc[m][npair]
    u64 a00 = 0ULL, a01 = 0ULL, a10 = 0ULL, a11 = 0ULL;
#pragma unroll
    for (int k = 0; k < 64; k += 4) {
        float4 qa = *(const float4*)(q_s + m0 * 68 + k);
        float4 qb = *(const float4*)(q_s + (m0 + 1) * 68 + k);
#pragma unroll
        for (int kk = 0; kk < 4; kk++) {
            const u64* kv = (const u64*)(kT + (k + kk) * 64 + n0);
            u64 k01 = kv[0], k23 = kv[1];
            float qav = (kk == 0) ? qa.x : (kk == 1) ? qa.y : (kk == 2) ? qa.z : qa.w;
            float qbv = (kk == 0) ? qb.x : (kk == 1) ? qb.y : (kk == 2) ? qb.z : qb.w;
            u64 qap = pk2(qav, qav);
            u64 qbp = pk2(qbv, qbv);
            fma2(a00, k01, qap);
            fma2(a01, k23, qap);
            fma2(a10, k01, qbp);
            fma2(a11, k23, qbp);
        }
    }
    float2 v00 = up2(a00), v01 = up2(a01), v10 = up2(a10), v11 = up2(a11);
    float p0[4] = {v00.x, v00.y, v01.x, v01.y};
    float p1[4] = {v10.x, v10.y, v11.x, v11.y};

    float am_m0 = amm_s[m0], am_m1 = amm_s[m0 + 1];
    float4 amn4 = *(const float4*)(amn_s + n0);
    float amn[4] = {amn4.x, amn4.y, amn4.z, amn4.w};
    int gm0 = m0g + m0, gm1 = gm0 + 1;
    int gn = n0g + n0;

    // pre = qk*0.125 - at - tr   (hoisted out of head loop; exact vs ref)
    float pre0[4], pre1[4];
#pragma unroll
    for (int j = 0; j < 4; j++) {
        float at0 = (1.0f - amn[j] * am_m0) * INF_F;
        float at1 = (1.0f - amn[j] * am_m1) * INF_F;
        float tr0 = (gn + j < gm0) ? INF_F : 0.f;
        float tr1 = (gn + j < gm1) ? INF_F : 0.f;
        pre0[j] = p0[j] * 0.125f - at0 - tr0;
        pre1[j] = p1[j] * 0.125f - at1 - tr1;
    }
    u64 pre0a = pk2(pre0[0], pre0[1]), pre0b = pk2(pre0[2], pre0[3]);
    u64 pre1a = pk2(pre1[0], pre1[1]), pre1b = pk2(pre1[2], pre1[3]);

    float* obase = out + (((size_t)b * 12 * 512 + gm0) * 512 + gn);
#pragma unroll
    for (int h = 0; h < 12; ++h) {
        const u64* bqp = (const u64*)(bq_s + h * 64 + n0);
        u64 bqa = bqp[0], bqb = bqp[1];
        float bk0 = bk_s[h * 32 + m0], bk1 = bk_s[h * 32 + m0 + 1];
        u64 bk0p = pk2(bk0, bk0), bk1p = pk2(bk1, bk1);

        u64 w0a = add2(add2(pre0a, bqa), bk0p);
        u64 w0b = add2(add2(pre0b, bqb), bk0p);
        u64 w1a = add2(add2(pre1a, bqa), bk1p);
        u64 w1b = add2(add2(pre1b, bqb), bk1p);

        float2 l0 = up2(w0a), h0 = up2(w0b);
        float2 l1 = up2(w1a), h1 = up2(w1b);
        float* o = obase + (size_t)h * 512 * 512;
        __stcs((float4*)o,         make_float4(l0.x, l0.y, h0.x, h0.y));
        __stcs((float4*)(o + 512), make_float4(l1.x, l1.y, h1.x, h1.y));
    }
}

// ================= launch =================
extern "C" void kernel_launch(void* const* d_in, const int* in_sizes, int n_in,
                              void* d_out, int out_size)
{
    const float* inp = (const float*)d_in[0];
    const float* am  = (const float*)d_in[1];
    const float* W1  = (const float*)d_in[2];
    const float* b1  = (const float*)d_in[3];
    const float* W2  = (const float*)d_in[4];
    const float* b2  = (const float*)d_in[5];
    float* out = (float*)d_out;

    k1_gemm<<<256, 128>>>(inp, W1, b1, W2, b2);
    k2_out<<<dim3(8, 16, 16), 256>>>(am, out);
}